// round 2
// baseline (speedup 1.0000x reference)
#include <cuda_runtime.h>

// FIR bandpass, zero-phase, reflect_limited padding — packed f32x2 version.
//
// Correlation form: out[t] = sum_{j=0}^{412} g[j] * xv[t-206+j],  g[j] = h[412-j]
// xv[m] = x[m]                    0 <= m < T
//       = 2*x[0]   - x[-m]        m < 0
//       = 2*x[T-1] - x[2T-2-m]    m >= T
//
// Each thread: 16 contiguous outputs t0..t0+15 (t0 = s + 16*tid), split into
// even (t0+2r) and odd (t0+2r+1) accumulator PAIRS (f32x2).
// Tap-pair step p (0..207, g zero-padded):
//   accE[r] += (g[2p],  g[2p+1]) * (xv[e], xv[e+1])      e = t0-206+2p+2r (even)
//   accO[r] += (g[2p-1],g[2p]  ) * (xv[e], xv[e+1])      same aligned pair!
// out = lane0 + lane1 of each accumulator pair.

#define T_LEN    30000
#define N_TAPS   413
#define HALF     206
#define TILE     3000
#define NTILES   10
#define NTHREADS 192
#define NSTEPS   208          // tap-pair steps (26 * 8), g padded with zeros
#define NPAIRS   1744         // logical xv pairs per block tile (q = 0..1743)
#define SV_PHYS  1961         // padded physical float2 count: 1743 + (1743>>3) + 1
#define F_MAX    3488         // logical floats = 2*NPAIRS

typedef unsigned long long u64;

__device__ __forceinline__ void dfma(u64& acc, u64 a, u64 b) {
    asm("fma.rn.f32x2 %0, %1, %2, %0;" : "+l"(acc) : "l"(a), "l"(b));
}
__device__ __forceinline__ void unpack2(float& lo, float& hi, u64 v) {
    asm("mov.b64 {%0, %1}, %2;" : "=f"(lo), "=f"(hi) : "l"(v));
}

__global__ __launch_bounds__(NTHREADS, 4)
void fir_bandpass_f32x2(const float* __restrict__ x,
                        const float* __restrict__ h,
                        float* __restrict__ out) {
    // padding: +1 float2 every 8 pairs -> lane stride 9 pairs -> conflict-free LDS.64
    __shared__ float2 sv[SV_PHYS];
    __shared__ float2 sgE[NSTEPS];   // (g[2p],   g[2p+1])
    __shared__ float2 sgO[NSTEPS];   // (g[2p-1], g[2p]  )

    const int row  = blockIdx.y;
    const int s    = blockIdx.x * TILE;
    const int tid  = threadIdx.x;

    const float* __restrict__ xr   = x   + (size_t)row * T_LEN;
    float* __restrict__       outr = out + (size_t)row * T_LEN;

    // ---- fill extended signal into padded smem (reflect_limited) ----
    const float x0 = xr[0];
    const float xl = xr[T_LEN - 1];
    float* svf = reinterpret_cast<float*>(sv);
    const int base_m = s - HALF;
    for (int f = tid; f < F_MAX; f += NTHREADS) {
        const int m = base_m + f;
        float v;
        if (m < 0)            v = 2.0f * x0 - xr[-m];
        else if (m >= T_LEN)  v = 2.0f * xl - xr[2 * T_LEN - 2 - m];
        else                  v = xr[m];
        svf[f + 2 * (f >> 4)] = v;   // physical float idx: 2*pidx(f>>1) + (f&1)
    }

    // ---- coefficient pairs, reversed taps: g[j] = h[412-j], zero-padded ----
    for (int p = tid; p < NSTEPS; p += NTHREADS) {
        const int j0 = 2 * p;
        const float ge_lo = (j0     <= 412) ? h[412 - j0]       : 0.0f;
        const float ge_hi = (j0 + 1 <= 412) ? h[412 - (j0 + 1)] : 0.0f;
        const float go_lo = (j0 >= 1)       ? h[412 - (j0 - 1)] : 0.0f;
        sgE[p] = make_float2(ge_lo, ge_hi);
        sgO[p] = make_float2(go_lo, ge_lo);
    }
    __syncthreads();

    // ---- main loop ----
    // thread's first window pair q0 = 8*tid; physical pidx(q0) = 9*tid
    const u64* Pw = reinterpret_cast<const u64*>(sv) + 9 * tid;
    const u64* cE = reinterpret_cast<const u64*>(sgE);
    const u64* cO = reinterpret_cast<const u64*>(sgO);

    u64 accE[8], accO[8];
#pragma unroll
    for (int r = 0; r < 8; ++r) { accE[r] = 0ull; accO[r] = 0ull; }

    // rolling window: slot (q & 7) holds pair q (q0 == 0 mod 8)
    u64 W[8];
#pragma unroll
    for (int r = 0; r < 8; ++r) W[r] = Pw[r];

    for (int i = 0; i < NSTEPS / 8; ++i) {
        const u64* pe = cE + 8 * i;
        const u64* po = cO + 8 * i;
        const u64* pw = Pw + 9 * i + 9;   // physical: pidx(q0 + 8(i+1) + u) = 9(i+1)+u
#pragma unroll
        for (int u = 0; u < 8; ++u) {
            const u64 ge = pe[u];
            const u64 go = po[u];
#pragma unroll
            for (int r = 0; r < 8; ++r) {
                const u64 wv = W[(u + r) & 7];
                dfma(accE[r], ge, wv);
                dfma(accO[r], go, wv);
            }
            W[u] = pw[u];                 // prefetch pair q0 + 8i + 8 + u
        }
    }

    // ---- horizontal add + store ----
    float res[16];
#pragma unroll
    for (int r = 0; r < 8; ++r) {
        float a, b, c, d;
        unpack2(a, b, accE[r]);
        unpack2(c, d, accO[r]);
        res[2 * r]     = a + b;
        res[2 * r + 1] = c + d;
    }

    const int t0 = s + 16 * tid;
#pragma unroll
    for (int gidx = 0; gidx < 4; ++gidx) {
        if (t0 + 4 * gidx + 3 < T_LEN) {
            *reinterpret_cast<float4*>(&outr[t0 + 4 * gidx]) =
                make_float4(res[4 * gidx], res[4 * gidx + 1],
                            res[4 * gidx + 2], res[4 * gidx + 3]);
        }
    }
}

extern "C" void kernel_launch(void* const* d_in, const int* in_sizes, int n_in,
                              void* d_out, int out_size) {
    const float* x = (const float*)d_in[0];   // (32, 64, 30000) f32
    const float* h = (const float*)d_in[1];   // (413,) f32
    float* out = (float*)d_out;

    dim3 grid(NTILES, 32 * 64);
    fir_bandpass_f32x2<<<grid, NTHREADS>>>(x, h, out);
}

// round 4
// speedup vs baseline: 1.3950x; 1.3950x over previous
#include <cuda_runtime.h>
#include <cuda_bf16.h>
#include <cstdint>

// FIR bandpass as banded-Toeplitz GEMM on mma.sync (bf16 hi/lo split, fp32 accum).
//
// out[t] = sum_j g[j] * xv[t-206+j],  g[j] = h[412-j]
// D[i,n] = sum_k A[i,k] * B[n,k],  A[i,k] = g[k-i]  (banded: 0 <= k-i <= 412)
// A fragment for (m-block mb, k-block kb) depends only on d = kb-mb:
//   A[16mb+r][16kb+c] = g[16d + c - r] = As[r][16d + c],  As = 16 x 448 strip.
// Split v = vh + vl (vl = bf16(v - vh), unscaled):
//   D = Ah.Bh + Ah.Bl + Al.Bh   (Al.Bl ~ 2^-18, dropped)

#define T_LEN    30000
#define NROWS    2048
#define HALF     206
#define M_TILE   128         // outputs per CTA (8 m16 blocks)
#define N_TILE   64          // signal rows per CTA
#define NKB      34          // k16 blocks (K = 544 = 128 + 412 pad16)
#define NCHUNK   9           // K chunks of 64 (last half-used)
#define DMAX     26          // valid Toeplitz block-diagonals: d in [0,26]
#define NTHREADS 256
#define NT_I0    235         // ceil(30000/128)

// ---- smem layout (bytes). As rows: 448 bf16 = 896B + 16 pad = 912.
//      Bs rows: 64 bf16 = 128B + 16 pad = 144.
#define OFF_ASH  0
#define OFF_ASL  14592
#define OFF_BSH  29184
#define OFF_BSL  38400
#define SMEM_REQ 47616
#define AS_STRIDE 912
#define BS_STRIDE 144
// epilogue staging reuses smem from offset 0: S[64][136] floats = 34816B

__device__ __forceinline__ uint32_t smem_u32(const void* p) {
    return (uint32_t)__cvta_generic_to_shared(p);
}

__device__ __forceinline__ void ldx4(uint32_t r[4], uint32_t addr) {
    asm volatile("ldmatrix.sync.aligned.m8n8.x4.shared.b16 {%0,%1,%2,%3}, [%4];"
                 : "=r"(r[0]), "=r"(r[1]), "=r"(r[2]), "=r"(r[3]) : "r"(addr));
}
__device__ __forceinline__ void ldx2(uint32_t r[2], uint32_t addr) {
    asm volatile("ldmatrix.sync.aligned.m8n8.x2.shared.b16 {%0,%1}, [%2];"
                 : "=r"(r[0]), "=r"(r[1]) : "r"(addr));
}
__device__ __forceinline__ void mma_bf16(float c[4], const uint32_t a[4],
                                         const uint32_t b[2]) {
    asm volatile(
        "mma.sync.aligned.m16n8k16.row.col.f32.bf16.bf16.f32 "
        "{%0,%1,%2,%3}, {%4,%5,%6,%7}, {%8,%9}, {%0,%1,%2,%3};"
        : "+f"(c[0]), "+f"(c[1]), "+f"(c[2]), "+f"(c[3])
        : "r"(a[0]), "r"(a[1]), "r"(a[2]), "r"(a[3]), "r"(b[0]), "r"(b[1]));
}

__device__ __forceinline__ uint32_t pack_hi(float a, float b) {
    __nv_bfloat162 p = __floats2bfloat162_rn(a, b);   // wait: need (lo=a, hi=b)
    return *reinterpret_cast<uint32_t*>(&p);
}

__global__ void __launch_bounds__(NTHREADS, 2)
fir_toeplitz_mma(const float* __restrict__ x,
                 const float* __restrict__ hcoef,
                 float* __restrict__ out) {
    extern __shared__ char smem[];
    const uint32_t sb = smem_u32(smem);
    const int tid  = threadIdx.x;
    const int wid  = tid >> 5;
    const int lane = tid & 31;
    const int wm   = wid >> 1;          // 0..3 : m rows [32*wm, 32*wm+32)
    const int wn   = wid & 1;           // 0..1 : n cols [32*wn, 32*wn+32)
    const int i0   = blockIdx.x;        // t tile: t = 128*i0 + i
    const int r0   = blockIdx.y * N_TILE;

    // ---- build Toeplitz coefficient strips (hi/lo bf16) ----
    for (int idx = tid; idx < 16 * 448; idx += NTHREADS) {
        const int r  = idx / 448;
        const int kq = idx - r * 448;
        const int j  = kq - r;
        const float gv = (j >= 0 && j <= 412) ? hcoef[412 - j] : 0.0f;
        const __nv_bfloat16 gh = __float2bfloat16(gv);
        const __nv_bfloat16 gl = __float2bfloat16(gv - __bfloat162float(gh));
        *reinterpret_cast<__nv_bfloat16*>(smem + OFF_ASH + r * AS_STRIDE + 2 * kq) = gh;
        *reinterpret_cast<__nv_bfloat16*>(smem + OFF_ASL + r * AS_STRIDE + 2 * kq) = gl;
    }

    // ---- per-thread constant addresses ----
    // A ldmatrix.x4: lanes 0-7 rows0-7/k0-7, 8-15 rows8-15/k0-7, 16-23 rows0-7/k8-15, 24-31 rows8-15/k8-15
    const uint32_t asl_off = (uint32_t)((lane & 15) * AS_STRIDE + ((lane >> 4) & 1) * 16);
    const uint32_t ash_base = sb + OFF_ASH + asl_off;
    const uint32_t asl_base = sb + OFF_ASL + asl_off;
    // B ldmatrix.x2: lanes 0-7 rows n0..n0+7 /k0-7, 8-15 same rows /k8-15
    const uint32_t bsl_off = (uint32_t)((32 * wn + (lane & 7)) * BS_STRIDE +
                                        ((lane >> 3) & 1) * 16);
    const uint32_t bsh_base = sb + OFF_BSH + bsl_off;
    const uint32_t bsl_base = sb + OFF_BSL + bsl_off;

    // B producer indices: thread -> (row n, 16-sample segment seg)
    const int bn   = tid >> 2;           // 0..63
    const int bseg = tid & 3;            // 0..3
    const float* __restrict__ xr = x + (size_t)(r0 + bn) * T_LEN;
    char* const bs_h_dst = smem + OFF_BSH + bn * BS_STRIDE + 32 * bseg;
    char* const bs_l_dst = smem + OFF_BSL + bn * BS_STRIDE + 32 * bseg;

    float acc[2][4][4];
#pragma unroll
    for (int b = 0; b < 2; ++b)
#pragma unroll
        for (int nb = 0; nb < 4; ++nb)
#pragma unroll
            for (int e = 0; e < 4; ++e) acc[b][nb][e] = 0.0f;

    // ================= main K loop =================
    for (int c = 0; c < NCHUNK; ++c) {
        // ---- producer: load 64 rows x 64 samples, split to bf16 hi/lo ----
        const int m0 = i0 * 128 - HALF + 64 * c + 16 * bseg;
        float v[16];
        if (m0 >= 0 && m0 + 16 <= T_LEN) {
#pragma unroll
            for (int e = 0; e < 8; ++e) {
                const float2 f = *reinterpret_cast<const float2*>(xr + m0 + 2 * e);
                v[2 * e] = f.x; v[2 * e + 1] = f.y;
            }
        } else {
#pragma unroll
            for (int e = 0; e < 16; ++e) {
                const int m = m0 + e;
                float t;
                if (m < 0)           t = 2.0f * xr[0] - xr[-m];
                else if (m >= T_LEN) t = 2.0f * xr[T_LEN - 1] - xr[2 * T_LEN - 2 - m];
                else                 t = xr[m];
                v[e] = t;
            }
        }
        uint32_t ph[8], pl[8];
#pragma unroll
        for (int e = 0; e < 8; ++e) {
            const float a = v[2 * e], bfl = v[2 * e + 1];
            const __nv_bfloat16 ah = __float2bfloat16(a);
            const __nv_bfloat16 bh = __float2bfloat16(bfl);
            const __nv_bfloat16 al = __float2bfloat16(a - __bfloat162float(ah));
            const __nv_bfloat16 bl = __float2bfloat16(bfl - __bfloat162float(bh));
            ph[e] = (uint32_t)__bfloat16_as_ushort(ah) |
                    ((uint32_t)__bfloat16_as_ushort(bh) << 16);
            pl[e] = (uint32_t)__bfloat16_as_ushort(al) |
                    ((uint32_t)__bfloat16_as_ushort(bl) << 16);
        }
        *reinterpret_cast<uint4*>(bs_h_dst)      = make_uint4(ph[0], ph[1], ph[2], ph[3]);
        *reinterpret_cast<uint4*>(bs_h_dst + 16) = make_uint4(ph[4], ph[5], ph[6], ph[7]);
        *reinterpret_cast<uint4*>(bs_l_dst)      = make_uint4(pl[0], pl[1], pl[2], pl[3]);
        *reinterpret_cast<uint4*>(bs_l_dst + 16) = make_uint4(pl[4], pl[5], pl[6], pl[7]);

        __syncthreads();

        // ---- consumer: 4 k16 steps ----
#pragma unroll
        for (int j = 0; j < 4; ++j) {
            const int kb = 4 * c + j;
            if (kb >= NKB) break;
            const int d0 = kb - 2 * wm;           // block 0 diag
            const int d1 = d0 - 1;                // block 1 diag
            const bool v0 = (d0 >= 0) && (d0 <= DMAX);
            const bool v1 = (d1 >= 0) && (d1 <= DMAX);
            if (!v0 && !v1) continue;

            uint32_t ah0[4], al0[4], ah1[4], al1[4];
            if (v0) { ldx4(ah0, ash_base + 32 * d0); ldx4(al0, asl_base + 32 * d0); }
            if (v1) { ldx4(ah1, ash_base + 32 * d1); ldx4(al1, asl_base + 32 * d1); }

#pragma unroll
            for (int nb = 0; nb < 4; ++nb) {
                uint32_t bh[2], bl[2];
                const uint32_t boff = (uint32_t)(nb * 8 * BS_STRIDE + 32 * j);
                ldx2(bh, bsh_base + boff);
                ldx2(bl, bsl_base + boff);
                if (v0) {
                    mma_bf16(acc[0][nb], ah0, bh);
                    mma_bf16(acc[0][nb], ah0, bl);
                    mma_bf16(acc[0][nb], al0, bh);
                }
                if (v1) {
                    mma_bf16(acc[1][nb], ah1, bh);
                    mma_bf16(acc[1][nb], ah1, bl);
                    mma_bf16(acc[1][nb], al1, bh);
                }
            }
        }
        __syncthreads();
    }

    // ================= epilogue: smem transpose -> coalesced stores =========
    float* S = reinterpret_cast<float*>(smem);    // S[n][t], stride 136 floats
#pragma unroll
    for (int b = 0; b < 2; ++b) {
#pragma unroll
        for (int nb = 0; nb < 4; ++nb) {
            const int tl = 32 * wm + 16 * b + (lane >> 2);
            const int nl = 32 * wn + 8 * nb + 2 * (lane & 3);
            S[nl * 136 + tl]           = acc[b][nb][0];
            S[(nl + 1) * 136 + tl]     = acc[b][nb][1];
            S[nl * 136 + tl + 8]       = acc[b][nb][2];
            S[(nl + 1) * 136 + tl + 8] = acc[b][nb][3];
        }
    }
    __syncthreads();

    const int tg = i0 * 128 + 4 * lane;
    if (tg < T_LEN) {
#pragma unroll
        for (int rr = 0; rr < 8; ++rr) {
            const int n = wid * 8 + rr;
            const float4 val = *reinterpret_cast<const float4*>(&S[n * 136 + 4 * lane]);
            *reinterpret_cast<float4*>(&out[(size_t)(r0 + n) * T_LEN + tg]) = val;
        }
    }
}

extern "C" void kernel_launch(void* const* d_in, const int* in_sizes, int n_in,
                              void* d_out, int out_size) {
    const float* x = (const float*)d_in[0];   // (32, 64, 30000) f32
    const float* h = (const float*)d_in[1];   // (413,) f32
    float* out = (float*)d_out;

    dim3 grid(NT_I0, NROWS / N_TILE);
    fir_toeplitz_mma<<<grid, NTHREADS, SMEM_REQ>>>(x, h, out);
}

// round 6
// speedup vs baseline: 1.6345x; 1.1717x over previous
#include <cuda_runtime.h>
#include <cuda_bf16.h>
#include <cstdint>

// FIR bandpass as banded-Toeplitz GEMM on mma.sync (bf16 hi/lo split, fp32 accum).
// R6 = R5 + cudaFuncSetAttribute (66KB dynamic smem needs opt-in; R5 launch failed).
//
// out[t] = sum_j g[j] * xv[t-206+j],  g[j] = h[412-j]
// D[i,n] = sum_k A[i,k] * B[n,k],  A[i,k] = g[k-i]  (banded: 0 <= k-i <= 412)
// A fragment for (mb, kb) depends only on d = kb-mb: strip As[r][16d + c].
// Split v = vh + vl (bf16):  D = Ah.Bh + Ah.Bl + Al.Bh

#define T_LEN    30000
#define NROWS    2048
#define HALF     206
#define M_TILE   128
#define N_TILE   64
#define NKB      34          // k16 blocks (K = 544)
#define NCHUNK   9           // chunks of 64 samples
#define DMAX     26
#define NTHREADS 256
#define NT_I0    235         // ceil(30000/128)

#define AS_STRIDE 912        // 448 bf16 + 16B pad
#define BS_STRIDE 144        // 64 bf16 + 16B pad
#define OFF_ASH  0
#define OFF_ASL  14592
#define OFF_BH0  29184
#define OFF_BL0  38400
#define OFF_BH1  47616
#define OFF_BL1  56832
#define SMEM_REQ 66048

__device__ __forceinline__ uint32_t smem_u32(const void* p) {
    return (uint32_t)__cvta_generic_to_shared(p);
}
__device__ __forceinline__ void ldx4(uint32_t r[4], uint32_t addr) {
    asm volatile("ldmatrix.sync.aligned.m8n8.x4.shared.b16 {%0,%1,%2,%3}, [%4];"
                 : "=r"(r[0]), "=r"(r[1]), "=r"(r[2]), "=r"(r[3]) : "r"(addr));
}
__device__ __forceinline__ void mma_bf16(float c[4], const uint32_t a[4],
                                         const uint32_t b0, const uint32_t b1) {
    asm volatile(
        "mma.sync.aligned.m16n8k16.row.col.f32.bf16.bf16.f32 "
        "{%0,%1,%2,%3}, {%4,%5,%6,%7}, {%8,%9}, {%0,%1,%2,%3};"
        : "+f"(c[0]), "+f"(c[1]), "+f"(c[2]), "+f"(c[3])
        : "r"(a[0]), "r"(a[1]), "r"(a[2]), "r"(a[3]), "r"(b0), "r"(b1));
}

__global__ void __launch_bounds__(NTHREADS, 2)
fir_toeplitz_mma(const float* __restrict__ x,
                 const float* __restrict__ hcoef,
                 float* __restrict__ out) {
    extern __shared__ char smem[];
    const uint32_t sb = smem_u32(smem);
    const int tid  = threadIdx.x;
    const int wid  = tid >> 5;
    const int lane = tid & 31;
    const int wm   = wid >> 1;           // 0..3
    const int wn   = wid & 1;            // 0..1
    const int i0   = blockIdx.x;
    const int r0   = blockIdx.y * N_TILE;

    // ---- build Toeplitz coefficient strips (hi/lo bf16) ----
    for (int idx = tid; idx < 16 * 448; idx += NTHREADS) {
        const int r  = idx / 448;
        const int kq = idx - r * 448;
        const int j  = kq - r;
        const float gv = (j >= 0 && j <= 412) ? hcoef[412 - j] : 0.0f;
        const __nv_bfloat16 gh = __float2bfloat16(gv);
        const __nv_bfloat16 gl = __float2bfloat16(gv - __bfloat162float(gh));
        *reinterpret_cast<__nv_bfloat16*>(smem + OFF_ASH + r * AS_STRIDE + 2 * kq) = gh;
        *reinterpret_cast<__nv_bfloat16*>(smem + OFF_ASL + r * AS_STRIDE + 2 * kq) = gl;
    }

    // ---- per-thread ldmatrix addresses ----
    const uint32_t asl_off = (uint32_t)((lane & 15) * AS_STRIDE + ((lane >> 4) & 1) * 16);
    const uint32_t ash_base = sb + OFF_ASH + asl_off;
    const uint32_t asl_base = sb + OFF_ASL + asl_off;
    // B x4 (nb pair): lanes 0-7 rows n0-7/+0, 8-15 n0-7/+16, 16-23 n8-15/+0, 24-31 n8-15/+16
    const uint32_t b_off = (uint32_t)((32 * wn + 8 * ((lane >> 4) & 1) + (lane & 7)) * BS_STRIDE
                                      + 16 * ((lane >> 3) & 1));

    // ---- producer mapping: thread -> (row n, 16-sample segment) ----
    const int bn   = tid >> 2;
    const int bseg = tid & 3;
    const float* __restrict__ xr = x + (size_t)(r0 + bn) * T_LEN;
    const uint32_t b_dst = (uint32_t)(bn * BS_STRIDE + 32 * bseg);

    float acc[2][4][4];
#pragma unroll
    for (int b = 0; b < 2; ++b)
#pragma unroll
        for (int nb = 0; nb < 4; ++nb)
#pragma unroll
            for (int e = 0; e < 4; ++e) acc[b][nb][e] = 0.0f;

    // ---- producer helpers ----
    auto load_chunk = [&](int c, float2 v[8]) {
        const int m0 = i0 * 128 - HALF + 64 * c + 16 * bseg;
        if (m0 >= 0 && m0 + 16 <= T_LEN) {
#pragma unroll
            for (int e = 0; e < 8; ++e)
                v[e] = *reinterpret_cast<const float2*>(xr + m0 + 2 * e);
        } else {
#pragma unroll
            for (int e = 0; e < 8; ++e) {
#pragma unroll
                for (int u = 0; u < 2; ++u) {
                    const int m = m0 + 2 * e + u;
                    float t;
                    if (m < 0)           t = 2.0f * xr[0] - xr[-m];
                    else if (m >= T_LEN) t = 2.0f * xr[T_LEN - 1] - xr[2 * T_LEN - 2 - m];
                    else                 t = xr[m];
                    (&v[e].x)[u] = t;
                }
            }
        }
    };
    auto store_chunk = [&](const float2 v[8], uint32_t off_h, uint32_t off_l) {
        uint32_t ph[8], pl[8];
#pragma unroll
        for (int e = 0; e < 8; ++e) {
            const float a = v[e].x, bb = v[e].y;
            const __nv_bfloat16 ah = __float2bfloat16(a);
            const __nv_bfloat16 bh = __float2bfloat16(bb);
            const __nv_bfloat16 al = __float2bfloat16(a - __bfloat162float(ah));
            const __nv_bfloat16 bl = __float2bfloat16(bb - __bfloat162float(bh));
            ph[e] = (uint32_t)__bfloat16_as_ushort(ah) | ((uint32_t)__bfloat16_as_ushort(bh) << 16);
            pl[e] = (uint32_t)__bfloat16_as_ushort(al) | ((uint32_t)__bfloat16_as_ushort(bl) << 16);
        }
        char* dh = smem + off_h + b_dst;
        char* dl = smem + off_l + b_dst;
        *reinterpret_cast<uint4*>(dh)      = make_uint4(ph[0], ph[1], ph[2], ph[3]);
        *reinterpret_cast<uint4*>(dh + 16) = make_uint4(ph[4], ph[5], ph[6], ph[7]);
        *reinterpret_cast<uint4*>(dl)      = make_uint4(pl[0], pl[1], pl[2], pl[3]);
        *reinterpret_cast<uint4*>(dl + 16) = make_uint4(pl[4], pl[5], pl[6], pl[7]);
    };

    // ---- prologue: produce chunk 0 into buf0 ----
    {
        float2 v[8];
        load_chunk(0, v);
        store_chunk(v, OFF_BH0, OFF_BL0);
    }
    __syncthreads();

    // rotation state: fragment for diagonal (kb-1 - 2wm), used by block1 at kb
    uint32_t ahp[4], alp[4];
    bool vp = false;

    // ---- main loop ----
    for (int c = 0; c < NCHUNK; ++c) {
        // LDG for next chunk issued early (latency hidden behind MMAs)
        float2 vstage[8];
        const bool have_next = (c + 1 < NCHUNK);
        if (have_next) load_chunk(c + 1, vstage);

        const uint32_t bh_buf = sb + ((c & 1) ? OFF_BH1 : OFF_BH0) + b_off;
        const uint32_t bl_buf = sb + ((c & 1) ? OFF_BL1 : OFF_BL0) + b_off;

#pragma unroll
        for (int j = 0; j < 4; ++j) {
            const int kb = 4 * c + j;
            if (kb >= NKB) break;
            const int d0 = kb - 2 * wm;
            const bool v0 = (d0 >= 0) && (d0 <= DMAX);

            uint32_t ah0[4], al0[4];
            if (v0) { ldx4(ah0, ash_base + 32 * d0); ldx4(al0, asl_base + 32 * d0); }

            if (v0 || vp) {
#pragma unroll
                for (int nbp = 0; nbp < 2; ++nbp) {
                    uint32_t bh[4], bl[4];   // [0,1]=frag nb=2nbp, [2,3]=frag nb=2nbp+1
                    const uint32_t boff = (uint32_t)(nbp * 16 * BS_STRIDE + 32 * j);
                    ldx4(bh, bh_buf + boff);
                    ldx4(bl, bl_buf + boff);
#pragma unroll
                    for (int s = 0; s < 2; ++s) {
                        const int nb = 2 * nbp + s;
                        if (v0) {
                            mma_bf16(acc[0][nb], ah0, bh[2 * s], bh[2 * s + 1]);
                            mma_bf16(acc[0][nb], ah0, bl[2 * s], bl[2 * s + 1]);
                            mma_bf16(acc[0][nb], al0, bh[2 * s], bh[2 * s + 1]);
                        }
                        if (vp) {
                            mma_bf16(acc[1][nb], ahp, bh[2 * s], bh[2 * s + 1]);
                            mma_bf16(acc[1][nb], ahp, bl[2 * s], bl[2 * s + 1]);
                            mma_bf16(acc[1][nb], alp, bh[2 * s], bh[2 * s + 1]);
                        }
                    }
                }
            }
            // rotate: block1 at kb+1 uses diagonal d0
#pragma unroll
            for (int e = 0; e < 4; ++e) { ahp[e] = ah0[e]; alp[e] = al0[e]; }
            vp = v0;
        }

        // produce next chunk into the other buffer, then one sync
        if (have_next)
            store_chunk(vstage, (c & 1) ? OFF_BH0 : OFF_BH1,
                                (c & 1) ? OFF_BL0 : OFF_BL1);
        __syncthreads();
    }

    // ---- epilogue: smem transpose -> coalesced float4 stores ----
    float* S = reinterpret_cast<float*>(smem);    // S[n][t], stride 136 floats
#pragma unroll
    for (int b = 0; b < 2; ++b) {
#pragma unroll
        for (int nb = 0; nb < 4; ++nb) {
            const int tl = 32 * wm + 16 * b + (lane >> 2);
            const int nl = 32 * wn + 8 * nb + 2 * (lane & 3);
            S[nl * 136 + tl]           = acc[b][nb][0];
            S[(nl + 1) * 136 + tl]     = acc[b][nb][1];
            S[nl * 136 + tl + 8]       = acc[b][nb][2];
            S[(nl + 1) * 136 + tl + 8] = acc[b][nb][3];
        }
    }
    __syncthreads();

    const int tg = i0 * 128 + 4 * lane;
    if (tg < T_LEN) {
#pragma unroll
        for (int rr = 0; rr < 8; ++rr) {
            const int n = wid * 8 + rr;
            const float4 val = *reinterpret_cast<const float4*>(&S[n * 136 + 4 * lane]);
            *reinterpret_cast<float4*>(&out[(size_t)(r0 + n) * T_LEN + tg]) = val;
        }
    }
}

extern "C" void kernel_launch(void* const* d_in, const int* in_sizes, int n_in,
                              void* d_out, int out_size) {
    const float* x = (const float*)d_in[0];   // (32, 64, 30000) f32
    const float* h = (const float*)d_in[1];   // (413,) f32
    float* out = (float*)d_out;

    // 66KB dynamic smem needs explicit opt-in (default cap is 48KB).
    // Not a prohibited API: no sync, no allocation, not stream-ordered.
    cudaFuncSetAttribute(fir_toeplitz_mma,
                         cudaFuncAttributeMaxDynamicSharedMemorySize, SMEM_REQ);

    dim3 grid(NT_I0, NROWS / N_TILE);
    fir_toeplitz_mma<<<grid, NTHREADS, SMEM_REQ>>>(x, h, out);
}

// round 7
// speedup vs baseline: 2.3350x; 1.4285x over previous
#include <cuda_runtime.h>
#include <cuda_fp16.h>
#include <cstdint>

// FIR bandpass as banded-Toeplitz GEMM on mma.sync — fp16 single-pass.
// R7: error budget allows pure fp16 (predicted rel_err ~3.4e-4 << 1e-3 norm-based).
// Per kb per warp: 8 MMA + 3 LDSM (was 24 + 6). B smem/STS halved. occ 3 CTAs/SM.
//
// out[t] = sum_j g[j] * xv[t-206+j],  g[j] = h[412-j]
// D[i,n] = sum_k A[i,k] * B[n,k],  A[i,k] = g[k-i]  (banded: 0 <= k-i <= 412)
// A fragment for (mb, kb) depends only on d = kb-mb: strip As[r][16d + c].

#define T_LEN    30000
#define NROWS    2048
#define HALF     206
#define N_TILE   64
#define NKB      34          // k16 blocks (K = 544)
#define NCHUNK   9           // chunks of 64 samples
#define DMAX     26
#define NTHREADS 256
#define NT_I0    235         // ceil(30000/128)

#define AS_STRIDE 912        // 448 fp16 + 16B pad
#define BS_STRIDE 144        // 64 fp16 + 16B pad
#define OFF_ASH  0           // 16 * 912 = 14592
#define OFF_BH0  14592       // 64 * 144 = 9216
#define OFF_BH1  23808
#define SMEM_REQ 35328       // epilogue staging needs 64*136*4 = 34816

__device__ __forceinline__ uint32_t smem_u32(const void* p) {
    return (uint32_t)__cvta_generic_to_shared(p);
}
__device__ __forceinline__ void ldx4(uint32_t r[4], uint32_t addr) {
    asm volatile("ldmatrix.sync.aligned.m8n8.x4.shared.b16 {%0,%1,%2,%3}, [%4];"
                 : "=r"(r[0]), "=r"(r[1]), "=r"(r[2]), "=r"(r[3]) : "r"(addr));
}
__device__ __forceinline__ void mma_f16(float c[4], const uint32_t a[4],
                                        const uint32_t b0, const uint32_t b1) {
    asm volatile(
        "mma.sync.aligned.m16n8k16.row.col.f32.f16.f16.f32 "
        "{%0,%1,%2,%3}, {%4,%5,%6,%7}, {%8,%9}, {%0,%1,%2,%3};"
        : "+f"(c[0]), "+f"(c[1]), "+f"(c[2]), "+f"(c[3])
        : "r"(a[0]), "r"(a[1]), "r"(a[2]), "r"(a[3]), "r"(b0), "r"(b1));
}

__global__ void __launch_bounds__(NTHREADS, 3)
fir_toeplitz_mma(const float* __restrict__ x,
                 const float* __restrict__ hcoef,
                 float* __restrict__ out) {
    extern __shared__ char smem[];
    const uint32_t sb = smem_u32(smem);
    const int tid  = threadIdx.x;
    const int wid  = tid >> 5;
    const int lane = tid & 31;
    const int wm   = wid >> 1;           // 0..3
    const int wn   = wid & 1;            // 0..1
    const int i0   = blockIdx.x;
    const int r0   = blockIdx.y * N_TILE;

    // ---- build Toeplitz coefficient strip (fp16) ----
    for (int idx = tid; idx < 16 * 448; idx += NTHREADS) {
        const int r  = idx / 448;
        const int kq = idx - r * 448;
        const int j  = kq - r;
        const float gv = (j >= 0 && j <= 412) ? hcoef[412 - j] : 0.0f;
        *reinterpret_cast<__half*>(smem + OFF_ASH + r * AS_STRIDE + 2 * kq) =
            __float2half_rn(gv);
    }

    // ---- per-thread ldmatrix addresses ----
    const uint32_t ash_base = sb + OFF_ASH +
        (uint32_t)((lane & 15) * AS_STRIDE + ((lane >> 4) & 1) * 16);
    // B x4 (nb pair): lanes 0-7 rows n0-7/+0, 8-15 n0-7/+16, 16-23 n8-15/+0, 24-31 n8-15/+16
    const uint32_t b_off = (uint32_t)((32 * wn + 8 * ((lane >> 4) & 1) + (lane & 7)) * BS_STRIDE
                                      + 16 * ((lane >> 3) & 1));

    // ---- producer mapping: thread -> (row n, 16-sample segment) ----
    const int bn   = tid >> 2;
    const int bseg = tid & 3;
    const float* __restrict__ xr = x + (size_t)(r0 + bn) * T_LEN;
    const uint32_t b_dst = (uint32_t)(bn * BS_STRIDE + 32 * bseg);

    float acc[2][4][4];
#pragma unroll
    for (int b = 0; b < 2; ++b)
#pragma unroll
        for (int nb = 0; nb < 4; ++nb)
#pragma unroll
            for (int e = 0; e < 4; ++e) acc[b][nb][e] = 0.0f;

    // ---- producer helpers ----
    auto load_chunk = [&](int c, float2 v[8]) {
        const int m0 = i0 * 128 - HALF + 64 * c + 16 * bseg;
        if (m0 >= 0 && m0 + 16 <= T_LEN) {
#pragma unroll
            for (int e = 0; e < 8; ++e)
                v[e] = *reinterpret_cast<const float2*>(xr + m0 + 2 * e);
        } else {
#pragma unroll
            for (int e = 0; e < 8; ++e) {
#pragma unroll
                for (int u = 0; u < 2; ++u) {
                    const int m = m0 + 2 * e + u;
                    float t;
                    if (m < 0)           t = 2.0f * xr[0] - xr[-m];
                    else if (m >= T_LEN) t = 2.0f * xr[T_LEN - 1] - xr[2 * T_LEN - 2 - m];
                    else                 t = xr[m];
                    (&v[e].x)[u] = t;
                }
            }
        }
    };
    auto store_chunk = [&](const float2 v[8], uint32_t off_h) {
        uint32_t ph[8];
#pragma unroll
        for (int e = 0; e < 8; ++e) {
            const __half2 p = __floats2half2_rn(v[e].x, v[e].y);
            ph[e] = *reinterpret_cast<const uint32_t*>(&p);
        }
        char* dh = smem + off_h + b_dst;
        *reinterpret_cast<uint4*>(dh)      = make_uint4(ph[0], ph[1], ph[2], ph[3]);
        *reinterpret_cast<uint4*>(dh + 16) = make_uint4(ph[4], ph[5], ph[6], ph[7]);
    };

    // ---- prologue: produce chunk 0 into buf0 ----
    {
        float2 v[8];
        load_chunk(0, v);
        store_chunk(v, OFF_BH0);
    }
    __syncthreads();

    // rotation state: fragment for diagonal (kb-1 - 2wm), used by block1 at kb
    uint32_t ahp[4];
    bool vp = false;

    // ---- main loop ----
    for (int c = 0; c < NCHUNK; ++c) {
        // LDG for next chunk issued early (latency hidden behind MMAs)
        float2 vstage[8];
        const bool have_next = (c + 1 < NCHUNK);
        if (have_next) load_chunk(c + 1, vstage);

        const uint32_t bh_buf = sb + ((c & 1) ? OFF_BH1 : OFF_BH0) + b_off;

#pragma unroll
        for (int j = 0; j < 4; ++j) {
            const int kb = 4 * c + j;
            if (kb >= NKB) break;
            const int d0 = kb - 2 * wm;
            const bool v0 = (d0 >= 0) && (d0 <= DMAX);

            uint32_t ah0[4];
            if (v0) ldx4(ah0, ash_base + 32 * d0);

            if (v0 || vp) {
#pragma unroll
                for (int nbp = 0; nbp < 2; ++nbp) {
                    uint32_t bh[4];   // [0,1]=frag nb=2nbp, [2,3]=frag nb=2nbp+1
                    const uint32_t boff = (uint32_t)(nbp * 16 * BS_STRIDE + 32 * j);
                    ldx4(bh, bh_buf + boff);
#pragma unroll
                    for (int s = 0; s < 2; ++s) {
                        const int nb = 2 * nbp + s;
                        if (v0) mma_f16(acc[0][nb], ah0, bh[2 * s], bh[2 * s + 1]);
                        if (vp) mma_f16(acc[1][nb], ahp, bh[2 * s], bh[2 * s + 1]);
                    }
                }
            }
            // rotate: block1 at kb+1 uses diagonal d0
#pragma unroll
            for (int e = 0; e < 4; ++e) ahp[e] = ah0[e];
            vp = v0;
        }

        // produce next chunk into the other buffer, then one sync
        if (have_next) store_chunk(vstage, (c & 1) ? OFF_BH0 : OFF_BH1);
        __syncthreads();
    }

    // ---- epilogue: smem transpose -> coalesced float4 stores ----
    float* S = reinterpret_cast<float*>(smem);    // S[n][t], stride 136 floats
#pragma unroll
    for (int b = 0; b < 2; ++b) {
#pragma unroll
        for (int nb = 0; nb < 4; ++nb) {
            const int tl = 32 * wm + 16 * b + (lane >> 2);
            const int nl = 32 * wn + 8 * nb + 2 * (lane & 3);
            S[nl * 136 + tl]           = acc[b][nb][0];
            S[(nl + 1) * 136 + tl]     = acc[b][nb][1];
            S[nl * 136 + tl + 8]       = acc[b][nb][2];
            S[(nl + 1) * 136 + tl + 8] = acc[b][nb][3];
        }
    }
    __syncthreads();

    const int tg = i0 * 128 + 4 * lane;
    if (tg < T_LEN) {
#pragma unroll
        for (int rr = 0; rr < 8; ++rr) {
            const int n = wid * 8 + rr;
            const float4 val = *reinterpret_cast<const float4*>(&S[n * 136 + 4 * lane]);
            *reinterpret_cast<float4*>(&out[(size_t)(r0 + n) * T_LEN + tg]) = val;
        }
    }
}

extern "C" void kernel_launch(void* const* d_in, const int* in_sizes, int n_in,
                              void* d_out, int out_size) {
    const float* x = (const float*)d_in[0];   // (32, 64, 30000) f32
    const float* h = (const float*)d_in[1];   // (413,) f32
    float* out = (float*)d_out;

    cudaFuncSetAttribute(fir_toeplitz_mma,
                         cudaFuncAttributeMaxDynamicSharedMemorySize, SMEM_REQ);

    dim3 grid(NT_I0, NROWS / N_TILE);
    fir_toeplitz_mma<<<grid, NTHREADS, SMEM_REQ>>>(x, h, out);
}

// round 8
// speedup vs baseline: 3.5658x; 1.5271x over previous
#include <cuda_runtime.h>
#include <cuda_fp16.h>
#include <cstdint>

// FIR bandpass as banded-Toeplitz GEMM on mma.sync — fp16, deep-M warps, cp.async.
// R8: 4 m-blocks/warp via static A-rotation ring (LDSM/MMA halved: 3 per 16 MMA),
//     reflect-extended fp16 signal prebuilt in __device__ global, producer = cp.async.
//
// out[t] = sum_j g[j] * xv[t-206+j],  g[j] = h[412-j]
// D[i,n] = sum_k A[i,k] * B[n,k],  A[i,k] = g[k-i]  (banded: 0 <= k-i <= 412)

#define T_LEN    30000
#define NROWS    2048
#define HALF     206
#define NKB      34            // k16 blocks (K = 544)
#define NCHUNK   9             // chunks of 64 samples
#define DMAX     26
#define NTHREADS 256
#define NT_I0    235           // ceil(30000/128)
#define EXT_STRIDE 30720       // halves per row (30412 used, padded, 16B-aligned)

#define AS_STRIDE 912          // 448 fp16 + 16B pad (57*16)
#define BS_STRIDE 144          // 64 fp16 + 16B pad (9*16)
#define OFF_AS   0             // 16 * 912 = 14592
#define OFF_B0   14592         // 128 * 144 = 18432
#define OFF_B1   33024
#define SMEM_REQ 51456

// reflect-extended fp16 signal: ext[row][e] = xv[row][e - 206]
__device__ __align__(16) __half g_ext[(size_t)NROWS * EXT_STRIDE];
// prebuilt Toeplitz strip, padded layout (16 rows x 912B)
__device__ __align__(16) char g_As[16 * AS_STRIDE];

__device__ __forceinline__ uint32_t smem_u32(const void* p) {
    return (uint32_t)__cvta_generic_to_shared(p);
}
__device__ __forceinline__ void ldx4(uint32_t r[4], uint32_t addr) {
    asm volatile("ldmatrix.sync.aligned.m8n8.x4.shared.b16 {%0,%1,%2,%3}, [%4];"
                 : "=r"(r[0]), "=r"(r[1]), "=r"(r[2]), "=r"(r[3]) : "r"(addr));
}
__device__ __forceinline__ void mma_f16(float c[4], const uint32_t a[4],
                                        const uint32_t b0, const uint32_t b1) {
    asm volatile(
        "mma.sync.aligned.m16n8k16.row.col.f32.f16.f16.f32 "
        "{%0,%1,%2,%3}, {%4,%5,%6,%7}, {%8,%9}, {%0,%1,%2,%3};"
        : "+f"(c[0]), "+f"(c[1]), "+f"(c[2]), "+f"(c[3])
        : "r"(a[0]), "r"(a[1]), "r"(a[2]), "r"(a[3]), "r"(b0), "r"(b1));
}
#define CP_ASYNC16(dst, src) \
    asm volatile("cp.async.cg.shared.global [%0], [%1], 16;" :: "r"(dst), "l"(src))
#define CP_COMMIT() asm volatile("cp.async.commit_group;" ::: "memory")
#define CP_WAIT(n)  asm volatile("cp.async.wait_group %0;" :: "n"(n) : "memory")

// ---------- pre-kernel 1: reflect-extended fp16 signal ----------
__global__ void build_ext(const float* __restrict__ x) {
    const int row = blockIdx.x;
    const float* __restrict__ xr = x + (size_t)row * T_LEN;
    __half* __restrict__ er = g_ext + (size_t)row * EXT_STRIDE;
    const float x0 = xr[0], xl = xr[T_LEN - 1];
    for (int e0 = 4 * threadIdx.x; e0 < EXT_STRIDE; e0 += 4 * 256) {
        __half v[4];
#pragma unroll
        for (int u = 0; u < 4; ++u) {
            const int m = e0 + u - HALF;
            float t;
            if (m < 0)           t = 2.0f * x0 - xr[-m];
            else if (m >= T_LEN) t = 2.0f * xl - xr[2 * T_LEN - 2 - m];
            else                 t = xr[m];
            v[u] = __float2half_rn(t);
        }
        *reinterpret_cast<uint2*>(er + e0) = *reinterpret_cast<const uint2*>(v);
    }
}

// ---------- pre-kernel 2: Toeplitz strip (padded layout) ----------
__global__ void build_as(const float* __restrict__ hcoef) {
    for (int idx = threadIdx.x; idx < 16 * 448; idx += 256) {
        const int r  = idx / 448;
        const int kq = idx - r * 448;
        const int j  = kq - r;
        const float gv = (j >= 0 && j <= 412) ? hcoef[412 - j] : 0.0f;
        *reinterpret_cast<__half*>(g_As + r * AS_STRIDE + 2 * kq) = __float2half_rn(gv);
    }
}

// ---------- main kernel ----------
__global__ void __launch_bounds__(NTHREADS, 2)
fir_mma(float* __restrict__ out) {
    extern __shared__ char smem[];
    const uint32_t sb = smem_u32(smem);
    const int tid  = threadIdx.x;
    const int wid  = tid >> 5;
    const int lane = tid & 31;
    const int wm   = wid >> 2;           // 0..1 : m-blocks 4wm..4wm+3 (t rows 64wm..)
    const int wn   = wid & 3;            // 0..3 : n cols [32wn, 32wn+32)
    const int i0   = blockIdx.x;
    const int r0   = blockIdx.y * 128;

    // ---- copy Toeplitz strip to smem ----
    {
        const uint4* src = reinterpret_cast<const uint4*>(g_As);
        uint4* dst = reinterpret_cast<uint4*>(smem + OFF_AS);
        for (int i = tid; i < (16 * AS_STRIDE) / 16; i += NTHREADS) dst[i] = src[i];
    }

    // ---- producer: thread -> (row, 32-sample segment), pure cp.async ----
    const int prow = tid >> 1;
    const int pseg = tid & 1;
    const __half* psrc = g_ext + (size_t)(r0 + prow) * EXT_STRIDE
                         + i0 * 128 + pseg * 32;
    const uint32_t pdst = sb + (uint32_t)(prow * BS_STRIDE + pseg * 64);

    // ---- consumer ldmatrix addresses ----
    const uint32_t as_base = sb + OFF_AS +
        (uint32_t)((lane & 15) * AS_STRIDE + ((lane >> 4) & 1) * 16);
    const uint32_t b_off = (uint32_t)((32 * wn + 8 * ((lane >> 4) & 1) + (lane & 7)) * BS_STRIDE
                                      + 16 * ((lane >> 3) & 1));

    float acc[4][4][4];
#pragma unroll
    for (int e = 0; e < 4; ++e)
#pragma unroll
        for (int nb = 0; nb < 4; ++nb)
#pragma unroll
            for (int q = 0; q < 4; ++q) acc[e][nb][q] = 0.0f;

    uint32_t af[4][4];                   // A-fragment rotation ring

    // prologue: chunk 0 in flight
    {
        const __half* s = psrc;
        const uint32_t d = pdst + OFF_B0;
#pragma unroll
        for (int q = 0; q < 4; ++q) CP_ASYNC16(d + 16 * q, s + 8 * q);
        CP_COMMIT();
    }

    for (int c = 0; c < NCHUNK; ++c) {
        if (c + 1 < NCHUNK) {
            const __half* s = psrc + 64 * (c + 1);
            const uint32_t d = pdst + (((c + 1) & 1) ? OFF_B1 : OFF_B0);
#pragma unroll
            for (int q = 0; q < 4; ++q) CP_ASYNC16(d + 16 * q, s + 8 * q);
            CP_COMMIT();
            CP_WAIT(1);                  // chunk c complete (c+1 may be pending)
        } else {
            CP_WAIT(0);
        }
        __syncthreads();

        const uint32_t bbuf = sb + ((c & 1) ? OFF_B1 : OFF_B0) + b_off;
        const int base = 4 * (c - wm);

#pragma unroll
        for (int j = 0; j < 4; ++j) {
            const int dnew = base + j;                     // diag for block e=0
            if ((unsigned)dnew <= (unsigned)DMAX)
                ldx4(af[j & 3], as_base + (dnew << 5));

            if (dnew >= 0 && dnew <= DMAX + 3) {           // some block valid
#pragma unroll
                for (int nbp = 0; nbp < 2; ++nbp) {
                    uint32_t bh[4];
                    ldx4(bh, bbuf + (uint32_t)(nbp * 16 * BS_STRIDE + 32 * j));
#pragma unroll
                    for (int s = 0; s < 2; ++s) {
                        const int nb = 2 * nbp + s;
#pragma unroll
                        for (int e = 0; e < 4; ++e)
                            if ((unsigned)(dnew - e) <= (unsigned)DMAX)
                                mma_f16(acc[e][nb], af[(j - e) & 3],
                                        bh[2 * s], bh[2 * s + 1]);
                    }
                }
            }
        }
        __syncthreads();
    }

    // ---- epilogue: 2 half-passes through smem transpose, coalesced stores ----
    float* S = reinterpret_cast<float*>(smem);    // S[n][t], stride 136 floats
    const int tg = i0 * 128 + 4 * lane;
#pragma unroll
    for (int hh = 0; hh < 2; ++hh) {
        if ((wn >> 1) == hh) {
#pragma unroll
            for (int e = 0; e < 4; ++e)
#pragma unroll
                for (int nb = 0; nb < 4; ++nb) {
                    const int tl = 64 * wm + 16 * e + (lane >> 2);
                    const int nl = 32 * (wn & 1) + 8 * nb + 2 * (lane & 3);
                    S[nl * 136 + tl]           = acc[e][nb][0];
                    S[(nl + 1) * 136 + tl]     = acc[e][nb][1];
                    S[nl * 136 + tl + 8]       = acc[e][nb][2];
                    S[(nl + 1) * 136 + tl + 8] = acc[e][nb][3];
                }
        }
        __syncthreads();
        if (tg < T_LEN) {
#pragma unroll
            for (int rr = 0; rr < 8; ++rr) {
                const int n = wid * 8 + rr;
                const float4 v = *reinterpret_cast<const float4*>(&S[n * 136 + 4 * lane]);
                *reinterpret_cast<float4*>(
                    &out[(size_t)(r0 + 64 * hh + n) * T_LEN + tg]) = v;
            }
        }
        __syncthreads();
    }
}

extern "C" void kernel_launch(void* const* d_in, const int* in_sizes, int n_in,
                              void* d_out, int out_size) {
    const float* x = (const float*)d_in[0];   // (32, 64, 30000) f32
    const float* h = (const float*)d_in[1];   // (413,) f32
    float* out = (float*)d_out;

    cudaFuncSetAttribute(fir_mma,
                         cudaFuncAttributeMaxDynamicSharedMemorySize, SMEM_REQ);

    build_ext<<<NROWS, 256>>>(x);
    build_as<<<1, 256>>>(h);

    dim3 grid(NT_I0, NROWS / 128);
    fir_mma<<<grid, NTHREADS, SMEM_REQ>>>(out);
}